// round 7
// baseline (speedup 1.0000x reference)
#include <cuda_runtime.h>
#include <cuda_fp16.h>
#include <cuda_bf16.h>
#include <math.h>
#include <stdint.h>

// ---------------------------------------------------------------------------
// GatingMixedDecoder: gate MLP -> softmax coeff -> 5 soft-mixed expert layers.
// mix(coeff,x,w) folded into one GEMM with K = E*d1, A scaled by coeff[b,k/d1].
// fp16 mma.sync m16n8k16 (f32 accumulate) — 2x the tf32 legacy rate, same
// 10-bit mantissa as tf32. Weights pre-transposed to fp16 [N][K] per launch.
// ---------------------------------------------------------------------------

#define Bsz    4096
#define LATENT 768
#define COND   512
#define HIDDEN 1024
#define OUTD   512
#define NEXP   8
#define GATE_H 512
#define INPUTD 1280   // LATENT+COND
#define INTERD 1792   // LATENT+HIDDEN
#define NEG_SLOPE 0.01f
#define LN_EPS 1e-5f

// ---- scratch (device globals; no allocation allowed) ----
__device__ float g_h1[Bsz * GATE_H];
__device__ float g_h2[Bsz * GATE_H];
__device__ float g_coeff[Bsz * NEXP];
__device__ float g_xn[Bsz * INTERD];
__device__ float g_lo[Bsz * HIDDEN];
__device__ float g_mixb[Bsz * HIDDEN];

// fp16 transposed weights, layout [N][K]
#define WT0_OFF   0ull                                   // [1024][10240]
#define WT1_OFF   (WT0_OFF + 1024ull * 10240ull)         // [1024][14336]
#define WT2_OFF   (WT1_OFF + 1024ull * 14336ull)
#define WT3_OFF   (WT2_OFF + 1024ull * 14336ull)
#define WT4_OFF   (WT3_OFF + 1024ull * 14336ull)         // [512][14336]
#define GWT0_OFF  (WT4_OFF + 512ull * 14336ull)          // [512][1280]
#define GWT1_OFF  (GWT0_OFF + 512ull * 1280ull)          // [512][512]
#define WT_TOTAL  (GWT1_OFF + 512ull * 512ull)
__device__ __half g_wt[WT_TOTAL];

__device__ __forceinline__ uint32_t smem_u32(const void* p) {
    uint32_t a;
    asm("{ .reg .u64 t; cvta.to.shared.u64 t, %1; cvt.u32.u64 %0, t; }" : "=r"(a) : "l"(p));
    return a;
}

// ---------------------------------------------------------------------------
// transpose + fp16 convert: out[c][r] = half(in[r][c]).  R%32==0, C%32==0.
// ---------------------------------------------------------------------------
__global__ void __launch_bounds__(256)
transpose_h_kernel(const float* __restrict__ in, __half* __restrict__ out, int R, int C)
{
    __shared__ float t[32][33];
    const int rb = blockIdx.y * 32, cb = blockIdx.x * 32;
    const int tx = threadIdx.x & 31, ty = threadIdx.x >> 5;   // 32x8
#pragma unroll
    for (int i = ty; i < 32; i += 8)
        t[i][tx] = in[(size_t)(rb + i) * C + cb + tx];
    __syncthreads();
#pragma unroll
    for (int i = ty; i < 32; i += 8)
        out[(size_t)(cb + i) * R + rb + tx] = __float2half_rn(t[tx][i]);
}

// ---------------------------------------------------------------------------
// fp16 tensor-core GEMM: C[M,N] = A[M,K] @ Bt[N,K]^T (+ epilogue), f32 accum.
// BM=128 BN=128 BK=32, 256 threads (8 warps), warp tile 64x32 (m16n8k16).
// Double-buffered dynamic smem; Bt via cp.async (pre-converted fp16);
// A via registers (fp32 load -> coeff scale -> fp16 convert).
// AMODE: 0 plain A1[M,K]; 1 concat(z[768], A2); 2 MoE coeff-scaled.
// EPI:   0 +bias[n],leaky; 1 +add[b,n],leaky; 2 +add[b,n]+resid,leaky; 3 +add[b,n].
// Requires M%128==0, N%128==0, K%32==0 (true at all call sites).
// ---------------------------------------------------------------------------
#define AH_STRIDE 40                       // halves per A row (32 + 8 pad)
#define BH_STRIDE 40                       // halves per Bt row (32 + 8 pad)
#define A_BYTES   (128 * AH_STRIDE * 2)    // 10240
#define B_BYTES   (128 * BH_STRIDE * 2)    // 10240
#define STAGE_BYTES (A_BYTES + B_BYTES)    // 20480
#define SMEM_TOTAL (2 * STAGE_BYTES)       // 40960

template <int AMODE, int EPI>
__global__ void __launch_bounds__(256)
h16gemm_kernel(const float* __restrict__ A1, const float* __restrict__ A2,
               const float* __restrict__ coeff, const __half* __restrict__ Bt,
               const float* __restrict__ addend, const float* __restrict__ resid,
               float* __restrict__ C, int M, int N, int K, int d1)
{
    extern __shared__ char smem[];
    const uint32_t smem_base = smem_u32(smem);

    const int tid  = threadIdx.x;
    const int warp = tid >> 5;
    const int lane = tid & 31;
    const int warp_m = (warp >> 2) * 64;
    const int warp_n = (warp & 3) * 32;
    const int grp = lane >> 2;     // 0..7
    const int tig = lane & 3;      // 0..3

    const int bm = blockIdx.y * 128;
    const int bn = blockIdx.x * 128;

    float acc[4][4][4];
#pragma unroll
    for (int i = 0; i < 4; i++)
#pragma unroll
        for (int j = 0; j < 4; j++)
#pragma unroll
            for (int r = 0; r < 4; r++) acc[i][j][r] = 0.f;

    float4 a_reg[4];

    // A tile (gmem, fp32): 128 rows x 32 cols = 1024 float4, 4/thread:
    //   row = idx>>3, c4 = idx&7
#define LOADA(k0)                                                               \
    {                                                                           \
        _Pragma("unroll")                                                       \
        for (int i = 0; i < 4; i++) {                                           \
            const int idx = tid + i * 256;                                      \
            const int row = idx >> 3, c4 = idx & 7;                             \
            const int gm = bm + row, gk = (k0) + c4 * 4;                        \
            if (AMODE == 0) {                                                   \
                a_reg[i] = *reinterpret_cast<const float4*>(A1 + (size_t)gm * K + gk); \
            } else if (AMODE == 1) {                                            \
                if (gk < LATENT)                                                \
                    a_reg[i] = *reinterpret_cast<const float4*>(A1 + (size_t)gm * LATENT + gk); \
                else                                                            \
                    a_reg[i] = *reinterpret_cast<const float4*>(A2 + (size_t)gm * (K - LATENT) + (gk - LATENT)); \
            } else {                                                            \
                const int e = gk / d1;                                          \
                const int j = gk - e * d1;                                      \
                const float cf = __ldg(coeff + gm * NEXP + e);                  \
                float4 x = *reinterpret_cast<const float4*>(A1 + (size_t)gm * d1 + j); \
                a_reg[i] = make_float4(x.x * cf, x.y * cf, x.z * cf, x.w * cf); \
            }                                                                   \
        }                                                                       \
    }

    // convert to fp16, store 8B (4 halves) per slot
#define STOREA(s)                                                               \
    {                                                                           \
        __half* Ah = reinterpret_cast<__half*>(smem + (s) * STAGE_BYTES);       \
        _Pragma("unroll")                                                       \
        for (int i = 0; i < 4; i++) {                                           \
            const int idx = tid + i * 256;                                      \
            const int row = idx >> 3, c4 = idx & 7;                             \
            __half2 h0 = __float22half2_rn(make_float2(a_reg[i].x, a_reg[i].y)); \
            __half2 h1 = __float22half2_rn(make_float2(a_reg[i].z, a_reg[i].w)); \
            uint2 pk = make_uint2(*reinterpret_cast<uint32_t*>(&h0),            \
                                  *reinterpret_cast<uint32_t*>(&h1));           \
            *reinterpret_cast<uint2*>(Ah + row * AH_STRIDE + c4 * 4) = pk;      \
        }                                                                       \
    }

    // Bt tile (gmem fp16, [N][K]): 128 rows x 32 halves = 512 x 16B, 2/thread:
    //   n = idx>>2, c4 = idx&3
#define CPB(s, k0)                                                              \
    {                                                                           \
        const uint32_t bbase = smem_base + (s) * STAGE_BYTES + A_BYTES;         \
        _Pragma("unroll")                                                       \
        for (int i = 0; i < 2; i++) {                                           \
            const int idx = tid + i * 256;                                      \
            const int n = idx >> 2, c4 = idx & 3;                               \
            const uint32_t dst = bbase + (uint32_t)(n * BH_STRIDE + c4 * 8) * 2; \
            const __half* src = Bt + (size_t)(bn + n) * K + (k0) + c4 * 8;      \
            asm volatile("cp.async.cg.shared.global [%0], [%1], 16;"            \
                         :: "r"(dst), "l"(src));                                \
        }                                                                       \
        asm volatile("cp.async.commit_group;");                                 \
    }

    const int nt = K >> 5;

    LOADA(0);
    CPB(0, 0);
    STOREA(0);
    asm volatile("cp.async.wait_group 0;");
    __syncthreads();

    for (int kt = 0; kt < nt; kt++) {
        const int s = kt & 1;
        if (kt + 1 < nt) {
            LOADA((kt + 1) << 5);
            CPB(s ^ 1, (kt + 1) << 5);
        }

        const __half* Ah = reinterpret_cast<const __half*>(smem + s * STAGE_BYTES);
        const __half* Bh = reinterpret_cast<const __half*>(smem + s * STAGE_BYTES + A_BYTES);

#pragma unroll
        for (int ks = 0; ks < 2; ks++) {
            const int kk = ks * 16;
            // B fragments: 4 n-tiles x 2 half2 regs (contiguous K in Bt rows)
            unsigned bfr[4][2];
#pragma unroll
            for (int ntt = 0; ntt < 4; ntt++) {
                const int n = warp_n + ntt * 8 + grp;
                bfr[ntt][0] = *reinterpret_cast<const unsigned*>(Bh + n * BH_STRIDE + kk + tig * 2);
                bfr[ntt][1] = *reinterpret_cast<const unsigned*>(Bh + n * BH_STRIDE + kk + tig * 2 + 8);
            }
            // A fragments: 4 m-tiles x 4 half2 regs
            unsigned afr[4][4];
#pragma unroll
            for (int mt = 0; mt < 4; mt++) {
                const int m = warp_m + mt * 16 + grp;
                afr[mt][0] = *reinterpret_cast<const unsigned*>(Ah + m * AH_STRIDE + kk + tig * 2);
                afr[mt][1] = *reinterpret_cast<const unsigned*>(Ah + (m + 8) * AH_STRIDE + kk + tig * 2);
                afr[mt][2] = *reinterpret_cast<const unsigned*>(Ah + m * AH_STRIDE + kk + tig * 2 + 8);
                afr[mt][3] = *reinterpret_cast<const unsigned*>(Ah + (m + 8) * AH_STRIDE + kk + tig * 2 + 8);
            }
#pragma unroll
            for (int mt = 0; mt < 4; mt++)
#pragma unroll
                for (int ntt = 0; ntt < 4; ntt++) {
                    asm volatile(
                        "mma.sync.aligned.m16n8k16.row.col.f32.f16.f16.f32 "
                        "{%0,%1,%2,%3}, {%4,%5,%6,%7}, {%8,%9}, {%0,%1,%2,%3};"
                        : "+f"(acc[mt][ntt][0]), "+f"(acc[mt][ntt][1]),
                          "+f"(acc[mt][ntt][2]), "+f"(acc[mt][ntt][3])
                        : "r"(afr[mt][0]), "r"(afr[mt][1]),
                          "r"(afr[mt][2]), "r"(afr[mt][3]),
                          "r"(bfr[ntt][0]), "r"(bfr[ntt][1]));
                }
        }

        if (kt + 1 < nt) STOREA(s ^ 1);
        asm volatile("cp.async.wait_group 0;");
        __syncthreads();
    }

    // ---- epilogue: c0,c1 at (row, col..col+1); c2,c3 at (row+8, ...) ----
#pragma unroll
    for (int mt = 0; mt < 4; mt++) {
        const int r0 = bm + warp_m + mt * 16 + grp;
#pragma unroll
        for (int ntt = 0; ntt < 4; ntt++) {
            const int c0 = bn + warp_n + ntt * 8 + tig * 2;
#pragma unroll
            for (int half = 0; half < 2; half++) {
                const int gr = r0 + half * 8;
                float v0 = acc[mt][ntt][half * 2 + 0];
                float v1 = acc[mt][ntt][half * 2 + 1];
                if (EPI == 0) {
                    const float2 ad = *reinterpret_cast<const float2*>(addend + c0);
                    v0 += ad.x; v1 += ad.y;
                } else {
                    const float2 ad = *reinterpret_cast<const float2*>(addend + (size_t)gr * N + c0);
                    v0 += ad.x; v1 += ad.y;
                }
                if (EPI == 2) {
                    const float2 rs = *reinterpret_cast<const float2*>(resid + (size_t)gr * N + c0);
                    v0 += rs.x; v1 += rs.y;
                }
                if (EPI != 3) {
                    v0 = (v0 > 0.f) ? v0 : NEG_SLOPE * v0;
                    v1 = (v1 > 0.f) ? v1 : NEG_SLOPE * v1;
                }
                *reinterpret_cast<float2*>(C + (size_t)gr * N + c0) = make_float2(v0, v1);
            }
        }
    }
#undef LOADA
#undef STOREA
#undef CPB
}

// ---------------------------------------------------------------------------
// LayerNorm over concat(z[768], src[srclen]); single pass, warp-shuffle reduce.
// ---------------------------------------------------------------------------
__global__ void __launch_bounds__(256)
ln_kernel(const float* __restrict__ z, const float* __restrict__ src, int srclen,
          const float* __restrict__ g, const float* __restrict__ b,
          float* __restrict__ out, int d)
{
    const int row = blockIdx.x;
    __shared__ float buf[INTERD];
    __shared__ float ws[8], wq[8];
    __shared__ float mu_s, rstd_s;
    const int tid = threadIdx.x, wid = tid >> 5, lane = tid & 31;

    float s = 0.f, sq = 0.f;
    for (int j = tid; j < d; j += 256) {
        float v = (j < LATENT) ? z[(size_t)row * LATENT + j]
                               : src[(size_t)row * srclen + (j - LATENT)];
        buf[j] = v;
        s += v; sq = fmaf(v, v, sq);
    }
#pragma unroll
    for (int o = 16; o > 0; o >>= 1) {
        s  += __shfl_down_sync(0xffffffffu, s, o);
        sq += __shfl_down_sync(0xffffffffu, sq, o);
    }
    if (lane == 0) { ws[wid] = s; wq[wid] = sq; }
    __syncthreads();
    if (tid == 0) {
        float S = 0.f, Q = 0.f;
#pragma unroll
        for (int i = 0; i < 8; i++) { S += ws[i]; Q += wq[i]; }
        const float mu = S / d;
        mu_s = mu;
        rstd_s = rsqrtf(Q / d - mu * mu + LN_EPS);
    }
    __syncthreads();
    const float mu = mu_s, rstd = rstd_s;
    for (int j = tid; j < d; j += 256)
        out[(size_t)row * d + j] = (buf[j] - mu) * rstd * g[j] + b[j];
}

// ---------------------------------------------------------------------------
// gate layer 3 + softmax (one warp per row)
// ---------------------------------------------------------------------------
__global__ void __launch_bounds__(256)
gate2_kernel(const float* __restrict__ h, const float* __restrict__ W,
             const float* __restrict__ bias, float* __restrict__ coeff)
{
    const int warp = (blockIdx.x * blockDim.x + threadIdx.x) >> 5;
    const int lane = threadIdx.x & 31;
    if (warp >= Bsz) return;

    float acc[NEXP];
#pragma unroll
    for (int e = 0; e < NEXP; e++) acc[e] = 0.f;
    for (int j = lane; j < GATE_H; j += 32) {
        const float hv = h[(size_t)warp * GATE_H + j];
        const float4 w0 = *reinterpret_cast<const float4*>(W + (size_t)j * NEXP);
        const float4 w1 = *reinterpret_cast<const float4*>(W + (size_t)j * NEXP + 4);
        acc[0] = fmaf(hv, w0.x, acc[0]); acc[1] = fmaf(hv, w0.y, acc[1]);
        acc[2] = fmaf(hv, w0.z, acc[2]); acc[3] = fmaf(hv, w0.w, acc[3]);
        acc[4] = fmaf(hv, w1.x, acc[4]); acc[5] = fmaf(hv, w1.y, acc[5]);
        acc[6] = fmaf(hv, w1.z, acc[6]); acc[7] = fmaf(hv, w1.w, acc[7]);
    }
#pragma unroll
    for (int e = 0; e < NEXP; e++)
#pragma unroll
        for (int o = 16; o > 0; o >>= 1)
            acc[e] += __shfl_down_sync(0xffffffffu, acc[e], o);
    if (lane == 0) {
        float v[NEXP], m = -1e30f;
#pragma unroll
        for (int e = 0; e < NEXP; e++) { v[e] = acc[e] + bias[e]; m = fmaxf(m, v[e]); }
        float sum = 0.f;
#pragma unroll
        for (int e = 0; e < NEXP; e++) { v[e] = __expf(v[e] - m); sum += v[e]; }
        const float inv = 1.f / sum;
#pragma unroll
        for (int e = 0; e < NEXP; e++) coeff[(size_t)warp * NEXP + e] = v[e] * inv;
    }
}

// ---------------------------------------------------------------------------
// mixed bias: mixb[b,n] = sum_e coeff[b,e] * bias[e,n]
// ---------------------------------------------------------------------------
__global__ void __launch_bounds__(256)
mixbias_kernel(const float* __restrict__ coeff, const float* __restrict__ bias,
               float* __restrict__ out, int N)
{
    const int idx = blockIdx.x * blockDim.x + threadIdx.x;
    if (idx >= Bsz * N) return;
    const int b = idx / N, n = idx - b * N;
    const float* cf = coeff + (size_t)b * NEXP;
    float s = 0.f;
#pragma unroll
    for (int e = 0; e < NEXP; e++) s = fmaf(cf[e], bias[(size_t)e * N + n], s);
    out[idx] = s;
}

// ---------------------------------------------------------------------------
extern "C" void kernel_launch(void* const* d_in, const int* in_sizes, int n_in,
                              void* d_out, int out_size)
{
    const float* z = (const float*)d_in[0];
    const float* c = (const float*)d_in[1];
    const float *w[5], *bb[5], *lng[5], *lnb[5], *gW[3], *gbv[3];

    const bool dict_order = (in_sizes[4] == INPUTD);
    if (dict_order) {
        for (int i = 0; i < 5; i++) {
            w[i]   = (const float*)d_in[2 + 4 * i];
            bb[i]  = (const float*)d_in[3 + 4 * i];
            lng[i] = (const float*)d_in[4 + 4 * i];
            lnb[i] = (const float*)d_in[5 + 4 * i];
        }
    } else {
        for (int i = 0; i < 5; i++) {
            w[i]   = (const float*)d_in[2 + 2 * i];
            bb[i]  = (const float*)d_in[3 + 2 * i];
            lng[i] = (const float*)d_in[12 + 2 * i];
            lnb[i] = (const float*)d_in[13 + 2 * i];
        }
    }
    for (int j = 0; j < 3; j++) {
        gW[j]  = (const float*)d_in[22 + 2 * j];
        gbv[j] = (const float*)d_in[23 + 2 * j];
    }

    float *h1, *h2, *coeff, *xn, *lo, *mixb;
    __half* wt;
    cudaGetSymbolAddress((void**)&h1,    g_h1);
    cudaGetSymbolAddress((void**)&h2,    g_h2);
    cudaGetSymbolAddress((void**)&coeff, g_coeff);
    cudaGetSymbolAddress((void**)&xn,    g_xn);
    cudaGetSymbolAddress((void**)&lo,    g_lo);
    cudaGetSymbolAddress((void**)&mixb,  g_mixb);
    cudaGetSymbolAddress((void**)&wt,    g_wt);

    cudaFuncSetAttribute(h16gemm_kernel<1, 0>, cudaFuncAttributeMaxDynamicSharedMemorySize, SMEM_TOTAL);
    cudaFuncSetAttribute(h16gemm_kernel<0, 0>, cudaFuncAttributeMaxDynamicSharedMemorySize, SMEM_TOTAL);
    cudaFuncSetAttribute(h16gemm_kernel<2, 1>, cudaFuncAttributeMaxDynamicSharedMemorySize, SMEM_TOTAL);
    cudaFuncSetAttribute(h16gemm_kernel<2, 2>, cudaFuncAttributeMaxDynamicSharedMemorySize, SMEM_TOTAL);
    cudaFuncSetAttribute(h16gemm_kernel<2, 3>, cudaFuncAttributeMaxDynamicSharedMemorySize, SMEM_TOTAL);

    // ---- pre-transpose + fp16-convert weights: [K][N] f32 -> [N][K] f16 ----
    {
        const struct { const float* src; uint64_t off; int R, C; } cv[7] = {
            { w[0],  WT0_OFF,  10240, 1024 },
            { w[1],  WT1_OFF,  14336, 1024 },
            { w[2],  WT2_OFF,  14336, 1024 },
            { w[3],  WT3_OFF,  14336, 1024 },
            { w[4],  WT4_OFF,  14336, 512  },
            { gW[0], GWT0_OFF, 1280,  512  },
            { gW[1], GWT1_OFF, 512,   512  },
        };
        for (int i = 0; i < 7; i++)
            transpose_h_kernel<<<dim3(cv[i].C / 32, cv[i].R / 32), 256>>>(
                cv[i].src, wt + cv[i].off, cv[i].R, cv[i].C);
    }

    // ---- gate MLP ----
    h16gemm_kernel<1, 0><<<dim3(GATE_H / 128, Bsz / 128), 256, SMEM_TOTAL>>>(
        z, c, nullptr, wt + GWT0_OFF, gbv[0], nullptr, h1, Bsz, GATE_H, INPUTD, 0);
    h16gemm_kernel<0, 0><<<dim3(GATE_H / 128, Bsz / 128), 256, SMEM_TOTAL>>>(
        h1, nullptr, nullptr, wt + GWT1_OFF, gbv[1], nullptr, h2, Bsz, GATE_H, GATE_H, 0);
    gate2_kernel<<<(Bsz * 32 + 255) / 256, 256>>>(h2, gW[2], gbv[2], coeff);

    // ---- layer 0 ----
    ln_kernel<<<Bsz, 256>>>(z, c, COND, lng[0], lnb[0], xn, INPUTD);
    mixbias_kernel<<<(Bsz * HIDDEN + 255) / 256, 256>>>(coeff, bb[0], mixb, HIDDEN);
    h16gemm_kernel<2, 1><<<dim3(HIDDEN / 128, Bsz / 128), 256, SMEM_TOTAL>>>(
        xn, nullptr, coeff, wt + WT0_OFF, mixb, nullptr, lo, Bsz, HIDDEN, NEXP * INPUTD, INPUTD);

    // ---- layers 1..3 (residual) ----
    const uint64_t wtoff[3] = { WT1_OFF, WT2_OFF, WT3_OFF };
    for (int i = 1; i <= 3; i++) {
        ln_kernel<<<Bsz, 256>>>(z, lo, HIDDEN, lng[i], lnb[i], xn, INTERD);
        mixbias_kernel<<<(Bsz * HIDDEN + 255) / 256, 256>>>(coeff, bb[i], mixb, HIDDEN);
        h16gemm_kernel<2, 2><<<dim3(HIDDEN / 128, Bsz / 128), 256, SMEM_TOTAL>>>(
            xn, nullptr, coeff, wt + wtoff[i - 1], mixb, lo, lo, Bsz, HIDDEN, NEXP * INTERD, INTERD);
    }

    // ---- final layer ----
    ln_kernel<<<Bsz, 256>>>(z, lo, HIDDEN, lng[4], lnb[4], xn, INTERD);
    mixbias_kernel<<<(Bsz * OUTD + 255) / 256, 256>>>(coeff, bb[4], mixb, OUTD);
    h16gemm_kernel<2, 3><<<dim3(OUTD / 128, Bsz / 128), 256, SMEM_TOTAL>>>(
        xn, nullptr, coeff, wt + WT4_OFF, mixb, nullptr, (float*)d_out, Bsz, OUTD, NEXP * INTERD, INTERD);
}

// round 8
// speedup vs baseline: 1.0037x; 1.0037x over previous
#include <cuda_runtime.h>
#include <cuda_fp16.h>
#include <cuda_bf16.h>
#include <math.h>
#include <stdint.h>

// ---------------------------------------------------------------------------
// GatingMixedDecoder: gate MLP -> softmax coeff -> 5 soft-mixed expert layers.
// mix(coeff,x,w) folded into one GEMM with K = E*d1, A scaled by coeff[b,k/d1].
// fp16 mma.sync m16n8k16 (f32 accumulate) — 2x the tf32 legacy rate, same
// 10-bit mantissa as tf32. Weights pre-transposed to fp16 [N][K] per launch.
// ---------------------------------------------------------------------------

#define Bsz    4096
#define LATENT 768
#define COND   512
#define HIDDEN 1024
#define OUTD   512
#define NEXP   8
#define GATE_H 512
#define INPUTD 1280   // LATENT+COND
#define INTERD 1792   // LATENT+HIDDEN
#define NEG_SLOPE 0.01f
#define LN_EPS 1e-5f

// ---- scratch (device globals; no allocation allowed) ----
__device__ float g_h1[Bsz * GATE_H];
__device__ float g_h2[Bsz * GATE_H];
__device__ float g_coeff[Bsz * NEXP];
__device__ float g_xn[Bsz * INTERD];
__device__ float g_lo[Bsz * HIDDEN];
__device__ float g_mixb[Bsz * HIDDEN];

// fp16 transposed weights, layout [N][K]
#define WT0_OFF   0ull                                   // [1024][10240]
#define WT1_OFF   (WT0_OFF + 1024ull * 10240ull)         // [1024][14336]
#define WT2_OFF   (WT1_OFF + 1024ull * 14336ull)
#define WT3_OFF   (WT2_OFF + 1024ull * 14336ull)
#define WT4_OFF   (WT3_OFF + 1024ull * 14336ull)         // [512][14336]
#define GWT0_OFF  (WT4_OFF + 512ull * 14336ull)          // [512][1280]
#define GWT1_OFF  (GWT0_OFF + 512ull * 1280ull)          // [512][512]
#define WT_TOTAL  (GWT1_OFF + 512ull * 512ull)
__device__ __half g_wt[WT_TOTAL];

__device__ __forceinline__ uint32_t smem_u32(const void* p) {
    uint32_t a;
    asm("{ .reg .u64 t; cvta.to.shared.u64 t, %1; cvt.u32.u64 %0, t; }" : "=r"(a) : "l"(p));
    return a;
}

// ---------------------------------------------------------------------------
// transpose + fp16 convert: out[c][r] = half(in[r][c]).  R%32==0, C%32==0.
// ---------------------------------------------------------------------------
__global__ void __launch_bounds__(256)
transpose_h_kernel(const float* __restrict__ in, __half* __restrict__ out, int R, int C)
{
    __shared__ float t[32][33];
    const int rb = blockIdx.y * 32, cb = blockIdx.x * 32;
    const int tx = threadIdx.x & 31, ty = threadIdx.x >> 5;   // 32x8
#pragma unroll
    for (int i = ty; i < 32; i += 8)
        t[i][tx] = in[(size_t)(rb + i) * C + cb + tx];
    __syncthreads();
#pragma unroll
    for (int i = ty; i < 32; i += 8)
        out[(size_t)(cb + i) * R + rb + tx] = __float2half_rn(t[tx][i]);
}

// ---------------------------------------------------------------------------
// fp16 tensor-core GEMM: C[M,N] = A[M,K] @ Bt[N,K]^T (+ epilogue), f32 accum.
// BM=128 BN=128 BK=32, 256 threads (8 warps), warp tile 64x32 (m16n8k16).
// Double-buffered dynamic smem; Bt via cp.async (pre-converted fp16);
// A via registers (fp32 load -> coeff scale -> fp16 convert).
// AMODE: 0 plain A1[M,K]; 1 concat(z[768], A2); 2 MoE coeff-scaled.
// EPI:   0 +bias[n],leaky; 1 +add[b,n],leaky; 2 +add[b,n]+resid,leaky; 3 +add[b,n].
// Requires M%128==0, N%128==0, K%32==0 (true at all call sites).
// ---------------------------------------------------------------------------
#define AH_STRIDE 40                       // halves per A row (32 + 8 pad)
#define BH_STRIDE 40                       // halves per Bt row (32 + 8 pad)
#define A_BYTES   (128 * AH_STRIDE * 2)    // 10240
#define B_BYTES   (128 * BH_STRIDE * 2)    // 10240
#define STAGE_BYTES (A_BYTES + B_BYTES)    // 20480
#define SMEM_TOTAL (2 * STAGE_BYTES)       // 40960

template <int AMODE, int EPI>
__global__ void __launch_bounds__(256)
h16gemm_kernel(const float* __restrict__ A1, const float* __restrict__ A2,
               const float* __restrict__ coeff, const __half* __restrict__ Bt,
               const float* __restrict__ addend, const float* __restrict__ resid,
               float* __restrict__ C, int M, int N, int K, int d1)
{
    extern __shared__ char smem[];
    const uint32_t smem_base = smem_u32(smem);

    const int tid  = threadIdx.x;
    const int warp = tid >> 5;
    const int lane = tid & 31;
    const int warp_m = (warp >> 2) * 64;
    const int warp_n = (warp & 3) * 32;
    const int grp = lane >> 2;     // 0..7
    const int tig = lane & 3;      // 0..3

    const int bm = blockIdx.y * 128;
    const int bn = blockIdx.x * 128;

    float acc[4][4][4];
#pragma unroll
    for (int i = 0; i < 4; i++)
#pragma unroll
        for (int j = 0; j < 4; j++)
#pragma unroll
            for (int r = 0; r < 4; r++) acc[i][j][r] = 0.f;

    float4 a_reg[4];

    // A tile (gmem, fp32): 128 rows x 32 cols = 1024 float4, 4/thread:
    //   row = idx>>3, c4 = idx&7
#define LOADA(k0)                                                               \
    {                                                                           \
        _Pragma("unroll")                                                       \
        for (int i = 0; i < 4; i++) {                                           \
            const int idx = tid + i * 256;                                      \
            const int row = idx >> 3, c4 = idx & 7;                             \
            const int gm = bm + row, gk = (k0) + c4 * 4;                        \
            if (AMODE == 0) {                                                   \
                a_reg[i] = *reinterpret_cast<const float4*>(A1 + (size_t)gm * K + gk); \
            } else if (AMODE == 1) {                                            \
                if (gk < LATENT)                                                \
                    a_reg[i] = *reinterpret_cast<const float4*>(A1 + (size_t)gm * LATENT + gk); \
                else                                                            \
                    a_reg[i] = *reinterpret_cast<const float4*>(A2 + (size_t)gm * (K - LATENT) + (gk - LATENT)); \
            } else {                                                            \
                const int e = gk / d1;                                          \
                const int j = gk - e * d1;                                      \
                const float cf = __ldg(coeff + gm * NEXP + e);                  \
                float4 x = *reinterpret_cast<const float4*>(A1 + (size_t)gm * d1 + j); \
                a_reg[i] = make_float4(x.x * cf, x.y * cf, x.z * cf, x.w * cf); \
            }                                                                   \
        }                                                                       \
    }

    // convert to fp16, store 8B (4 halves) per slot
#define STOREA(s)                                                               \
    {                                                                           \
        __half* Ah = reinterpret_cast<__half*>(smem + (s) * STAGE_BYTES);       \
        _Pragma("unroll")                                                       \
        for (int i = 0; i < 4; i++) {                                           \
            const int idx = tid + i * 256;                                      \
            const int row = idx >> 3, c4 = idx & 7;                             \
            __half2 h0 = __float22half2_rn(make_float2(a_reg[i].x, a_reg[i].y)); \
            __half2 h1 = __float22half2_rn(make_float2(a_reg[i].z, a_reg[i].w)); \
            uint2 pk = make_uint2(*reinterpret_cast<uint32_t*>(&h0),            \
                                  *reinterpret_cast<uint32_t*>(&h1));           \
            *reinterpret_cast<uint2*>(Ah + row * AH_STRIDE + c4 * 4) = pk;      \
        }                                                                       \
    }

    // Bt tile (gmem fp16, [N][K]): 128 rows x 32 halves = 512 x 16B, 2/thread:
    //   n = idx>>2, c4 = idx&3
#define CPB(s, k0)                                                              \
    {                                                                           \
        const uint32_t bbase = smem_base + (s) * STAGE_BYTES + A_BYTES;         \
        _Pragma("unroll")                                                       \
        for (int i = 0; i < 2; i++) {                                           \
            const int idx = tid + i * 256;                                      \
            const int n = idx >> 2, c4 = idx & 3;                               \
            const uint32_t dst = bbase + (uint32_t)(n * BH_STRIDE + c4 * 8) * 2; \
            const __half* src = Bt + (size_t)(bn + n) * K + (k0) + c4 * 8;      \
            asm volatile("cp.async.cg.shared.global [%0], [%1], 16;"            \
                         :: "r"(dst), "l"(src));                                \
        }                                                                       \
        asm volatile("cp.async.commit_group;");                                 \
    }

    const int nt = K >> 5;

    LOADA(0);
    CPB(0, 0);
    STOREA(0);
    asm volatile("cp.async.wait_group 0;");
    __syncthreads();

    for (int kt = 0; kt < nt; kt++) {
        const int s = kt & 1;
        if (kt + 1 < nt) {
            LOADA((kt + 1) << 5);
            CPB(s ^ 1, (kt + 1) << 5);
        }

        const __half* Ah = reinterpret_cast<const __half*>(smem + s * STAGE_BYTES);
        const __half* Bh = reinterpret_cast<const __half*>(smem + s * STAGE_BYTES + A_BYTES);

#pragma unroll
        for (int ks = 0; ks < 2; ks++) {
            const int kk = ks * 16;
            // B fragments: 4 n-tiles x 2 half2 regs (contiguous K in Bt rows)
            unsigned bfr[4][2];
#pragma unroll
            for (int ntt = 0; ntt < 4; ntt++) {
                const int n = warp_n + ntt * 8 + grp;
                bfr[ntt][0] = *reinterpret_cast<const unsigned*>(Bh + n * BH_STRIDE + kk + tig * 2);
                bfr[ntt][1] = *reinterpret_cast<const unsigned*>(Bh + n * BH_STRIDE + kk + tig * 2 + 8);
            }
            // A fragments: 4 m-tiles x 4 half2 regs
            unsigned afr[4][4];
#pragma unroll
            for (int mt = 0; mt < 4; mt++) {
                const int m = warp_m + mt * 16 + grp;
                afr[mt][0] = *reinterpret_cast<const unsigned*>(Ah + m * AH_STRIDE + kk + tig * 2);
                afr[mt][1] = *reinterpret_cast<const unsigned*>(Ah + (m + 8) * AH_STRIDE + kk + tig * 2);
                afr[mt][2] = *reinterpret_cast<const unsigned*>(Ah + m * AH_STRIDE + kk + tig * 2 + 8);
                afr[mt][3] = *reinterpret_cast<const unsigned*>(Ah + (m + 8) * AH_STRIDE + kk + tig * 2 + 8);
            }
#pragma unroll
            for (int mt = 0; mt < 4; mt++)
#pragma unroll
                for (int ntt = 0; ntt < 4; ntt++) {
                    asm volatile(
                        "mma.sync.aligned.m16n8k16.row.col.f32.f16.f16.f32 "
                        "{%0,%1,%2,%3}, {%4,%5,%6,%7}, {%8,%9}, {%0,%1,%2,%3};"
                        : "+f"(acc[mt][ntt][0]), "+f"(acc[mt][ntt][1]),
                          "+f"(acc[mt][ntt][2]), "+f"(acc[mt][ntt][3])
                        : "r"(afr[mt][0]), "r"(afr[mt][1]),
                          "r"(afr[mt][2]), "r"(afr[mt][3]),
                          "r"(bfr[ntt][0]), "r"(bfr[ntt][1]));
                }
        }

        if (kt + 1 < nt) STOREA(s ^ 1);
        asm volatile("cp.async.wait_group 0;");
        __syncthreads();
    }

    // ---- epilogue: c0,c1 at (row, col..col+1); c2,c3 at (row+8, ...) ----
#pragma unroll
    for (int mt = 0; mt < 4; mt++) {
        const int r0 = bm + warp_m + mt * 16 + grp;
#pragma unroll
        for (int ntt = 0; ntt < 4; ntt++) {
            const int c0 = bn + warp_n + ntt * 8 + tig * 2;
#pragma unroll
            for (int half = 0; half < 2; half++) {
                const int gr = r0 + half * 8;
                float v0 = acc[mt][ntt][half * 2 + 0];
                float v1 = acc[mt][ntt][half * 2 + 1];
                if (EPI == 0) {
                    const float2 ad = *reinterpret_cast<const float2*>(addend + c0);
                    v0 += ad.x; v1 += ad.y;
                } else {
                    const float2 ad = *reinterpret_cast<const float2*>(addend + (size_t)gr * N + c0);
                    v0 += ad.x; v1 += ad.y;
                }
                if (EPI == 2) {
                    const float2 rs = *reinterpret_cast<const float2*>(resid + (size_t)gr * N + c0);
                    v0 += rs.x; v1 += rs.y;
                }
                if (EPI != 3) {
                    v0 = (v0 > 0.f) ? v0 : NEG_SLOPE * v0;
                    v1 = (v1 > 0.f) ? v1 : NEG_SLOPE * v1;
                }
                *reinterpret_cast<float2*>(C + (size_t)gr * N + c0) = make_float2(v0, v1);
            }
        }
    }
#undef LOADA
#undef STOREA
#undef CPB
}

// ---------------------------------------------------------------------------
// LayerNorm over concat(z[768], src[srclen]); single pass, warp-shuffle reduce.
// ---------------------------------------------------------------------------
__global__ void __launch_bounds__(256)
ln_kernel(const float* __restrict__ z, const float* __restrict__ src, int srclen,
          const float* __restrict__ g, const float* __restrict__ b,
          float* __restrict__ out, int d)
{
    const int row = blockIdx.x;
    __shared__ float buf[INTERD];
    __shared__ float ws[8], wq[8];
    __shared__ float mu_s, rstd_s;
    const int tid = threadIdx.x, wid = tid >> 5, lane = tid & 31;

    float s = 0.f, sq = 0.f;
    for (int j = tid; j < d; j += 256) {
        float v = (j < LATENT) ? z[(size_t)row * LATENT + j]
                               : src[(size_t)row * srclen + (j - LATENT)];
        buf[j] = v;
        s += v; sq = fmaf(v, v, sq);
    }
#pragma unroll
    for (int o = 16; o > 0; o >>= 1) {
        s  += __shfl_down_sync(0xffffffffu, s, o);
        sq += __shfl_down_sync(0xffffffffu, sq, o);
    }
    if (lane == 0) { ws[wid] = s; wq[wid] = sq; }
    __syncthreads();
    if (tid == 0) {
        float S = 0.f, Q = 0.f;
#pragma unroll
        for (int i = 0; i < 8; i++) { S += ws[i]; Q += wq[i]; }
        const float mu = S / d;
        mu_s = mu;
        rstd_s = rsqrtf(Q / d - mu * mu + LN_EPS);
    }
    __syncthreads();
    const float mu = mu_s, rstd = rstd_s;
    for (int j = tid; j < d; j += 256)
        out[(size_t)row * d + j] = (buf[j] - mu) * rstd * g[j] + b[j];
}

// ---------------------------------------------------------------------------
// gate layer 3 + softmax (one warp per row)
// ---------------------------------------------------------------------------
__global__ void __launch_bounds__(256)
gate2_kernel(const float* __restrict__ h, const float* __restrict__ W,
             const float* __restrict__ bias, float* __restrict__ coeff)
{
    const int warp = (blockIdx.x * blockDim.x + threadIdx.x) >> 5;
    const int lane = threadIdx.x & 31;
    if (warp >= Bsz) return;

    float acc[NEXP];
#pragma unroll
    for (int e = 0; e < NEXP; e++) acc[e] = 0.f;
    for (int j = lane; j < GATE_H; j += 32) {
        const float hv = h[(size_t)warp * GATE_H + j];
        const float4 w0 = *reinterpret_cast<const float4*>(W + (size_t)j * NEXP);
        const float4 w1 = *reinterpret_cast<const float4*>(W + (size_t)j * NEXP + 4);
        acc[0] = fmaf(hv, w0.x, acc[0]); acc[1] = fmaf(hv, w0.y, acc[1]);
        acc[2] = fmaf(hv, w0.z, acc[2]); acc[3] = fmaf(hv, w0.w, acc[3]);
        acc[4] = fmaf(hv, w1.x, acc[4]); acc[5] = fmaf(hv, w1.y, acc[5]);
        acc[6] = fmaf(hv, w1.z, acc[6]); acc[7] = fmaf(hv, w1.w, acc[7]);
    }
#pragma unroll
    for (int e = 0; e < NEXP; e++)
#pragma unroll
        for (int o = 16; o > 0; o >>= 1)
            acc[e] += __shfl_down_sync(0xffffffffu, acc[e], o);
    if (lane == 0) {
        float v[NEXP], m = -1e30f;
#pragma unroll
        for (int e = 0; e < NEXP; e++) { v[e] = acc[e] + bias[e]; m = fmaxf(m, v[e]); }
        float sum = 0.f;
#pragma unroll
        for (int e = 0; e < NEXP; e++) { v[e] = __expf(v[e] - m); sum += v[e]; }
        const float inv = 1.f / sum;
#pragma unroll
        for (int e = 0; e < NEXP; e++) coeff[(size_t)warp * NEXP + e] = v[e] * inv;
    }
}

// ---------------------------------------------------------------------------
// mixed bias: mixb[b,n] = sum_e coeff[b,e] * bias[e,n]
// ---------------------------------------------------------------------------
__global__ void __launch_bounds__(256)
mixbias_kernel(const float* __restrict__ coeff, const float* __restrict__ bias,
               float* __restrict__ out, int N)
{
    const int idx = blockIdx.x * blockDim.x + threadIdx.x;
    if (idx >= Bsz * N) return;
    const int b = idx / N, n = idx - b * N;
    const float* cf = coeff + (size_t)b * NEXP;
    float s = 0.f;
#pragma unroll
    for (int e = 0; e < NEXP; e++) s = fmaf(cf[e], bias[(size_t)e * N + n], s);
    out[idx] = s;
}

// ---------------------------------------------------------------------------
extern "C" void kernel_launch(void* const* d_in, const int* in_sizes, int n_in,
                              void* d_out, int out_size)
{
    const float* z = (const float*)d_in[0];
    const float* c = (const float*)d_in[1];
    const float *w[5], *bb[5], *lng[5], *lnb[5], *gW[3], *gbv[3];

    const bool dict_order = (in_sizes[4] == INPUTD);
    if (dict_order) {
        for (int i = 0; i < 5; i++) {
            w[i]   = (const float*)d_in[2 + 4 * i];
            bb[i]  = (const float*)d_in[3 + 4 * i];
            lng[i] = (const float*)d_in[4 + 4 * i];
            lnb[i] = (const float*)d_in[5 + 4 * i];
        }
    } else {
        for (int i = 0; i < 5; i++) {
            w[i]   = (const float*)d_in[2 + 2 * i];
            bb[i]  = (const float*)d_in[3 + 2 * i];
            lng[i] = (const float*)d_in[12 + 2 * i];
            lnb[i] = (const float*)d_in[13 + 2 * i];
        }
    }
    for (int j = 0; j < 3; j++) {
        gW[j]  = (const float*)d_in[22 + 2 * j];
        gbv[j] = (const float*)d_in[23 + 2 * j];
    }

    float *h1, *h2, *coeff, *xn, *lo, *mixb;
    __half* wt;
    cudaGetSymbolAddress((void**)&h1,    g_h1);
    cudaGetSymbolAddress((void**)&h2,    g_h2);
    cudaGetSymbolAddress((void**)&coeff, g_coeff);
    cudaGetSymbolAddress((void**)&xn,    g_xn);
    cudaGetSymbolAddress((void**)&lo,    g_lo);
    cudaGetSymbolAddress((void**)&mixb,  g_mixb);
    cudaGetSymbolAddress((void**)&wt,    g_wt);

    cudaFuncSetAttribute(h16gemm_kernel<1, 0>, cudaFuncAttributeMaxDynamicSharedMemorySize, SMEM_TOTAL);
    cudaFuncSetAttribute(h16gemm_kernel<0, 0>, cudaFuncAttributeMaxDynamicSharedMemorySize, SMEM_TOTAL);
    cudaFuncSetAttribute(h16gemm_kernel<2, 1>, cudaFuncAttributeMaxDynamicSharedMemorySize, SMEM_TOTAL);
    cudaFuncSetAttribute(h16gemm_kernel<2, 2>, cudaFuncAttributeMaxDynamicSharedMemorySize, SMEM_TOTAL);
    cudaFuncSetAttribute(h16gemm_kernel<2, 3>, cudaFuncAttributeMaxDynamicSharedMemorySize, SMEM_TOTAL);

    // ---- pre-transpose + fp16-convert weights: [K][N] f32 -> [N][K] f16 ----
    {
        const struct { const float* src; uint64_t off; int R, C; } cv[7] = {
            { w[0],  WT0_OFF,  10240, 1024 },
            { w[1],  WT1_OFF,  14336, 1024 },
            { w[2],  WT2_OFF,  14336, 1024 },
            { w[3],  WT3_OFF,  14336, 1024 },
            { w[4],  WT4_OFF,  14336, 512  },
            { gW[0], GWT0_OFF, 1280,  512  },
            { gW[1], GWT1_OFF, 512,   512  },
        };
        for (int i = 0; i < 7; i++)
            transpose_h_kernel<<<dim3(cv[i].C / 32, cv[i].R / 32), 256>>>(
                cv[i].src, wt + cv[i].off, cv[i].R, cv[i].C);
    }

    // ---- gate MLP ----
    h16gemm_kernel<1, 0><<<dim3(GATE_H / 128, Bsz / 128), 256, SMEM_TOTAL>>>(
        z, c, nullptr, wt + GWT0_OFF, gbv[0], nullptr, h1, Bsz, GATE_H, INPUTD, 0);
    h16gemm_kernel<0, 0><<<dim3(GATE_H / 128, Bsz / 128), 256, SMEM_TOTAL>>>(
        h1, nullptr, nullptr, wt + GWT1_OFF, gbv[1], nullptr, h2, Bsz, GATE_H, GATE_H, 0);
    gate2_kernel<<<(Bsz * 32 + 255) / 256, 256>>>(h2, gW[2], gbv[2], coeff);

    // ---- layer 0 ----
    ln_kernel<<<Bsz, 256>>>(z, c, COND, lng[0], lnb[0], xn, INPUTD);
    mixbias_kernel<<<(Bsz * HIDDEN + 255) / 256, 256>>>(coeff, bb[0], mixb, HIDDEN);
    h16gemm_kernel<2, 1><<<dim3(HIDDEN / 128, Bsz / 128), 256, SMEM_TOTAL>>>(
        xn, nullptr, coeff, wt + WT0_OFF, mixb, nullptr, lo, Bsz, HIDDEN, NEXP * INPUTD, INPUTD);

    // ---- layers 1..3 (residual) ----
    const uint64_t wtoff[3] = { WT1_OFF, WT2_OFF, WT3_OFF };
    for (int i = 1; i <= 3; i++) {
        ln_kernel<<<Bsz, 256>>>(z, lo, HIDDEN, lng[i], lnb[i], xn, INTERD);
        mixbias_kernel<<<(Bsz * HIDDEN + 255) / 256, 256>>>(coeff, bb[i], mixb, HIDDEN);
        h16gemm_kernel<2, 2><<<dim3(HIDDEN / 128, Bsz / 128), 256, SMEM_TOTAL>>>(
            xn, nullptr, coeff, wt + wtoff[i - 1], mixb, lo, lo, Bsz, HIDDEN, NEXP * INTERD, INTERD);
    }

    // ---- final layer ----
    ln_kernel<<<Bsz, 256>>>(z, lo, HIDDEN, lng[4], lnb[4], xn, INTERD);
    mixbias_kernel<<<(Bsz * OUTD + 255) / 256, 256>>>(coeff, bb[4], mixb, OUTD);
    h16gemm_kernel<2, 3><<<dim3(OUTD / 128, Bsz / 128), 256, SMEM_TOTAL>>>(
        xn, nullptr, coeff, wt + WT4_OFF, mixb, nullptr, (float*)d_out, Bsz, OUTD, NEXP * INTERD, INTERD);
}

// round 14
// speedup vs baseline: 1.0164x; 1.0127x over previous
#include <cuda_runtime.h>
#include <cuda_fp16.h>
#include <cuda_bf16.h>
#include <math.h>
#include <stdint.h>

// ---------------------------------------------------------------------------
// GatingMixedDecoder: gate MLP -> softmax coeff -> 5 soft-mixed expert layers.
// mix(coeff,x,w) folded into one GEMM with K = E*d1, A scaled by coeff[b,k/d1].
// fp16 mma m16n8k16, f32 accumulate. LayerNorm fused into the A-load (stats
// precomputed per row); mixed expert bias fused into the epilogue.
// Layer activations ping-pong between two buffers: the fused LN A-load reads
// the FULL previous-layer row during the mainloop, so input and output of a
// layer GEMM must be distinct buffers (same-buffer use raced in R13).
// ---------------------------------------------------------------------------

#define Bsz    4096
#define LATENT 768
#define COND   512
#define HIDDEN 1024
#define OUTD   512
#define NEXP   8
#define GATE_H 512
#define INPUTD 1280   // LATENT+COND
#define INTERD 1792   // LATENT+HIDDEN
#define NEG_SLOPE 0.01f
#define LN_EPS 1e-5f

// ---- scratch (device globals; no allocation allowed) ----
__device__ float  g_h1[Bsz * GATE_H];
__device__ float  g_h2[Bsz * GATE_H];
__device__ float  g_coeff[Bsz * NEXP];
__device__ float  g_loA[Bsz * HIDDEN];
__device__ float  g_loB[Bsz * HIDDEN];
__device__ float2 g_stats[Bsz];

// fp16 transposed weights, layout [N][K]
#define WT0_OFF   0ull                                   // [1024][10240]
#define WT1_OFF   (WT0_OFF + 1024ull * 10240ull)         // [1024][14336]
#define WT2_OFF   (WT1_OFF + 1024ull * 14336ull)
#define WT3_OFF   (WT2_OFF + 1024ull * 14336ull)
#define WT4_OFF   (WT3_OFF + 1024ull * 14336ull)         // [512][14336]
#define GWT0_OFF  (WT4_OFF + 512ull * 14336ull)          // [512][1280]
#define GWT1_OFF  (GWT0_OFF + 512ull * 1280ull)          // [512][512]
#define WT_TOTAL  (GWT1_OFF + 512ull * 512ull)
__device__ __half g_wt[WT_TOTAL];

__device__ __forceinline__ uint32_t smem_u32(const void* p) {
    uint32_t a;
    asm("{ .reg .u64 t; cvta.to.shared.u64 t, %1; cvt.u32.u64 %0, t; }" : "=r"(a) : "l"(p));
    return a;
}

// ---------------------------------------------------------------------------
// transpose + fp16 convert: out[c][r] = half(in[r][c]).  R%32==0, C%32==0.
// ---------------------------------------------------------------------------
__global__ void __launch_bounds__(256)
transpose_h_kernel(const float* __restrict__ in, __half* __restrict__ out, int R, int C)
{
    __shared__ float t[32][33];
    const int rb = blockIdx.y * 32, cb = blockIdx.x * 32;
    const int tx = threadIdx.x & 31, ty = threadIdx.x >> 5;   // 32x8
#pragma unroll
    for (int i = ty; i < 32; i += 8)
        t[i][tx] = in[(size_t)(rb + i) * C + cb + tx];
    __syncthreads();
#pragma unroll
    for (int i = ty; i < 32; i += 8)
        out[(size_t)(cb + i) * R + rb + tx] = __float2half_rn(t[tx][i]);
}

// ---------------------------------------------------------------------------
// per-row LN stats over concat(z[768], src[srclen]): stats[row] = (mu, rstd)
// ---------------------------------------------------------------------------
__global__ void __launch_bounds__(256)
ln_stats_kernel(const float* __restrict__ z, const float* __restrict__ src,
                int srclen, float2* __restrict__ stats, int d)
{
    const int row = blockIdx.x;
    __shared__ float ws[8], wq[8];
    const int tid = threadIdx.x, wid = tid >> 5, lane = tid & 31;

    float s = 0.f, sq = 0.f;
    for (int j = tid; j < d; j += 256) {
        float v = (j < LATENT) ? z[(size_t)row * LATENT + j]
                               : src[(size_t)row * srclen + (j - LATENT)];
        s += v; sq = fmaf(v, v, sq);
    }
#pragma unroll
    for (int o = 16; o > 0; o >>= 1) {
        s  += __shfl_down_sync(0xffffffffu, s, o);
        sq += __shfl_down_sync(0xffffffffu, sq, o);
    }
    if (lane == 0) { ws[wid] = s; wq[wid] = sq; }
    __syncthreads();
    if (tid == 0) {
        float S = 0.f, Q = 0.f;
#pragma unroll
        for (int i = 0; i < 8; i++) { S += ws[i]; Q += wq[i]; }
        const float mu = S / d;
        stats[row] = make_float2(mu, rsqrtf(Q / d - mu * mu + LN_EPS));
    }
}

// ---------------------------------------------------------------------------
// fp16 tensor-core GEMM (f32 accum): C[M,N] = A[M,K] @ Bt[N,K]^T (+ epilogue)
// BM=128 BN=128 BK=32, 256 threads (8 warps), warp tile 64x32 (m16n8k16).
// Double-buffered smem; Bt via cp.async (fp16); A via registers.
// AMODE 0: plain A1[M,K].
// AMODE 1: concat(z[768], A2).
// AMODE 2: MoE, LN fused: a = coeff[b,e] * (lng*(x-mu)*rstd + lnb),
//          x = concat(z, A2)[jj].   NOTE: A2 must NOT alias C.
// EPI 0: + addend[n] (gate bias), leaky.
// EPI 1: + sum_e coeff[b,e]*biasE[e][n], leaky.          (addend = biasE[E][N])
// EPI 2: + mixed bias + resid[b,n], leaky.   (resid may alias A2: per-element)
// EPI 3: + mixed bias, no activation.
// ---------------------------------------------------------------------------
#define AH_STRIDE 40                       // halves per A row (32 + 8 pad)
#define BH_STRIDE 40                       // halves per Bt row (32 + 8 pad)
#define A_BYTES   (128 * AH_STRIDE * 2)    // 10240
#define B_BYTES   (128 * BH_STRIDE * 2)    // 10240
#define STAGE_BYTES (A_BYTES + B_BYTES)    // 20480
#define BIAS_BYTES  (NEXP * 128 * 4)       // 4096
#define SMEM_TOTAL (2 * STAGE_BYTES + BIAS_BYTES)   // 45056

template <int AMODE, int EPI>
__global__ void __launch_bounds__(256)
h16gemm_kernel(const float* __restrict__ A1, const float* __restrict__ A2,
               const float* __restrict__ coeff, const __half* __restrict__ Bt,
               const float* __restrict__ addend, const float* __restrict__ resid,
               const float* __restrict__ lng, const float* __restrict__ lnb,
               const float2* __restrict__ stats,
               float* __restrict__ C, int M, int N, int K, int d1)
{
    extern __shared__ char smem[];
    const uint32_t smem_base = smem_u32(smem);
    float* bs = reinterpret_cast<float*>(smem + 2 * STAGE_BYTES);  // [8][128]

    const int tid  = threadIdx.x;
    const int warp = tid >> 5;
    const int lane = tid & 31;
    const int warp_m = (warp >> 2) * 64;
    const int warp_n = (warp & 3) * 32;
    const int grp = lane >> 2;     // 0..7
    const int tig = lane & 3;      // 0..3

    const int bm = blockIdx.y * 128;
    const int bn = blockIdx.x * 128;

    // stage expert-bias tile into smem (EPI 1..3): bs[e][n] = biasE[e][bn+n]
    if (EPI != 0) {
        const int r = tid >> 5, cc = (tid & 31) * 4;
        *reinterpret_cast<float4*>(bs + r * 128 + cc) =
            *reinterpret_cast<const float4*>(addend + (size_t)r * N + bn + cc);
    }

    float acc[4][4][4];
#pragma unroll
    for (int i = 0; i < 4; i++)
#pragma unroll
        for (int j = 0; j < 4; j++)
#pragma unroll
            for (int r = 0; r < 4; r++) acc[i][j][r] = 0.f;

    float4 a_reg[4];

    // A tile (gmem fp32): 128 rows x 32 cols = 1024 float4, 4/thread
#define LOADA(k0)                                                               \
    {                                                                           \
        _Pragma("unroll")                                                       \
        for (int i = 0; i < 4; i++) {                                           \
            const int idx = tid + i * 256;                                      \
            const int row = idx >> 3, c4 = idx & 7;                             \
            const int gm = bm + row, gk = (k0) + c4 * 4;                        \
            if (AMODE == 0) {                                                   \
                a_reg[i] = *reinterpret_cast<const float4*>(A1 + (size_t)gm * K + gk); \
            } else if (AMODE == 1) {                                            \
                if (gk < LATENT)                                                \
                    a_reg[i] = *reinterpret_cast<const float4*>(A1 + (size_t)gm * LATENT + gk); \
                else                                                            \
                    a_reg[i] = *reinterpret_cast<const float4*>(A2 + (size_t)gm * (K - LATENT) + (gk - LATENT)); \
            } else {                                                            \
                const int e = gk / d1;                                          \
                const int jj = gk - e * d1;                                     \
                const float cf = __ldg(coeff + gm * NEXP + e);                  \
                const float2 st = __ldg(stats + gm);                            \
                float4 x;                                                       \
                if (jj < LATENT)                                                \
                    x = *reinterpret_cast<const float4*>(A1 + (size_t)gm * LATENT + jj); \
                else                                                            \
                    x = *reinterpret_cast<const float4*>(A2 + (size_t)gm * (d1 - LATENT) + (jj - LATENT)); \
                const float4 gg = *reinterpret_cast<const float4*>(lng + jj);   \
                const float4 bv = *reinterpret_cast<const float4*>(lnb + jj);   \
                x.x = cf * fmaf((x.x - st.x) * st.y, gg.x, bv.x);               \
                x.y = cf * fmaf((x.y - st.x) * st.y, gg.y, bv.y);               \
                x.z = cf * fmaf((x.z - st.x) * st.y, gg.z, bv.z);               \
                x.w = cf * fmaf((x.w - st.x) * st.y, gg.w, bv.w);               \
                a_reg[i] = x;                                                   \
            }                                                                   \
        }                                                                       \
    }

#define STOREA(s)                                                               \
    {                                                                           \
        __half* Ah = reinterpret_cast<__half*>(smem + (s) * STAGE_BYTES);       \
        _Pragma("unroll")                                                       \
        for (int i = 0; i < 4; i++) {                                           \
            const int idx = tid + i * 256;                                      \
            const int row = idx >> 3, c4 = idx & 7;                             \
            __half2 h0 = __float22half2_rn(make_float2(a_reg[i].x, a_reg[i].y)); \
            __half2 h1 = __float22half2_rn(make_float2(a_reg[i].z, a_reg[i].w)); \
            uint2 pk = make_uint2(*reinterpret_cast<uint32_t*>(&h0),            \
                                  *reinterpret_cast<uint32_t*>(&h1));           \
            *reinterpret_cast<uint2*>(Ah + row * AH_STRIDE + c4 * 4) = pk;      \
        }                                                                       \
    }

#define CPB(s, k0)                                                              \
    {                                                                           \
        const uint32_t bbase = smem_base + (s) * STAGE_BYTES + A_BYTES;         \
        _Pragma("unroll")                                                       \
        for (int i = 0; i < 2; i++) {                                           \
            const int idx = tid + i * 256;                                      \
            const int n = idx >> 2, c4 = idx & 3;                               \
            const uint32_t dst = bbase + (uint32_t)(n * BH_STRIDE + c4 * 8) * 2; \
            const __half* src = Bt + (size_t)(bn + n) * K + (k0) + c4 * 8;      \
            asm volatile("cp.async.cg.shared.global [%0], [%1], 16;"            \
                         :: "r"(dst), "l"(src));                                \
        }                                                                       \
        asm volatile("cp.async.commit_group;");                                 \
    }

    const int nt = K >> 5;

    LOADA(0);
    CPB(0, 0);
    STOREA(0);
    asm volatile("cp.async.wait_group 0;");
    __syncthreads();

    for (int kt = 0; kt < nt; kt++) {
        const int s = kt & 1;
        if (kt + 1 < nt) {
            LOADA((kt + 1) << 5);
            CPB(s ^ 1, (kt + 1) << 5);
        }

        const __half* Ah = reinterpret_cast<const __half*>(smem + s * STAGE_BYTES);
        const __half* Bh = reinterpret_cast<const __half*>(smem + s * STAGE_BYTES + A_BYTES);

#pragma unroll
        for (int ks = 0; ks < 2; ks++) {
            const int kk = ks * 16;
            unsigned bfr[4][2];
#pragma unroll
            for (int ntt = 0; ntt < 4; ntt++) {
                const int n = warp_n + ntt * 8 + grp;
                bfr[ntt][0] = *reinterpret_cast<const unsigned*>(Bh + n * BH_STRIDE + kk + tig * 2);
                bfr[ntt][1] = *reinterpret_cast<const unsigned*>(Bh + n * BH_STRIDE + kk + tig * 2 + 8);
            }
            unsigned afr[4][4];
#pragma unroll
            for (int mt = 0; mt < 4; mt++) {
                const int m = warp_m + mt * 16 + grp;
                afr[mt][0] = *reinterpret_cast<const unsigned*>(Ah + m * AH_STRIDE + kk + tig * 2);
                afr[mt][1] = *reinterpret_cast<const unsigned*>(Ah + (m + 8) * AH_STRIDE + kk + tig * 2);
                afr[mt][2] = *reinterpret_cast<const unsigned*>(Ah + m * AH_STRIDE + kk + tig * 2 + 8);
                afr[mt][3] = *reinterpret_cast<const unsigned*>(Ah + (m + 8) * AH_STRIDE + kk + tig * 2 + 8);
            }
#pragma unroll
            for (int mt = 0; mt < 4; mt++)
#pragma unroll
                for (int ntt = 0; ntt < 4; ntt++) {
                    asm volatile(
                        "mma.sync.aligned.m16n8k16.row.col.f32.f16.f16.f32 "
                        "{%0,%1,%2,%3}, {%4,%5,%6,%7}, {%8,%9}, {%0,%1,%2,%3};"
                        : "+f"(acc[mt][ntt][0]), "+f"(acc[mt][ntt][1]),
                          "+f"(acc[mt][ntt][2]), "+f"(acc[mt][ntt][3])
                        : "r"(afr[mt][0]), "r"(afr[mt][1]),
                          "r"(afr[mt][2]), "r"(afr[mt][3]),
                          "r"(bfr[ntt][0]), "r"(bfr[ntt][1]));
                }
        }

        if (kt + 1 < nt) STOREA(s ^ 1);
        asm volatile("cp.async.wait_group 0;");
        __syncthreads();
    }

    // ---- epilogue ----
#pragma unroll
    for (int mt = 0; mt < 4; mt++) {
        const int r0 = bm + warp_m + mt * 16 + grp;
#pragma unroll
        for (int half = 0; half < 2; half++) {
            const int gr = r0 + half * 8;
            float cf[NEXP];
            if (EPI != 0) {
                const float4 c0v = __ldg(reinterpret_cast<const float4*>(coeff + (size_t)gr * NEXP));
                const float4 c1v = __ldg(reinterpret_cast<const float4*>(coeff + (size_t)gr * NEXP + 4));
                cf[0] = c0v.x; cf[1] = c0v.y; cf[2] = c0v.z; cf[3] = c0v.w;
                cf[4] = c1v.x; cf[5] = c1v.y; cf[6] = c1v.z; cf[7] = c1v.w;
            }
#pragma unroll
            for (int ntt = 0; ntt < 4; ntt++) {
                const int ln0 = warp_n + ntt * 8 + tig * 2;   // local col in [0,128)
                const int c0 = bn + ln0;
                float v0 = acc[mt][ntt][half * 2 + 0];
                float v1 = acc[mt][ntt][half * 2 + 1];
                if (EPI == 0) {
                    const float2 ad = *reinterpret_cast<const float2*>(addend + c0);
                    v0 += ad.x; v1 += ad.y;
                } else {
#pragma unroll
                    for (int e = 0; e < NEXP; e++) {
                        v0 = fmaf(cf[e], bs[e * 128 + ln0], v0);
                        v1 = fmaf(cf[e], bs[e * 128 + ln0 + 1], v1);
                    }
                }
                if (EPI == 2) {
                    const float2 rs = *reinterpret_cast<const float2*>(resid + (size_t)gr * N + c0);
                    v0 += rs.x; v1 += rs.y;
                }
                if (EPI != 3) {
                    v0 = (v0 > 0.f) ? v0 : NEG_SLOPE * v0;
                    v1 = (v1 > 0.f) ? v1 : NEG_SLOPE * v1;
                }
                *reinterpret_cast<float2*>(C + (size_t)gr * N + c0) = make_float2(v0, v1);
            }
        }
    }
#undef LOADA
#undef STOREA
#undef CPB
}

// ---------------------------------------------------------------------------
// gate layer 3 + softmax (one warp per row)
// ---------------------------------------------------------------------------
__global__ void __launch_bounds__(256)
gate2_kernel(const float* __restrict__ h, const float* __restrict__ W,
             const float* __restrict__ bias, float* __restrict__ coeff)
{
    const int warp = (blockIdx.x * blockDim.x + threadIdx.x) >> 5;
    const int lane = threadIdx.x & 31;
    if (warp >= Bsz) return;

    float acc[NEXP];
#pragma unroll
    for (int e = 0; e < NEXP; e++) acc[e] = 0.f;
    for (int j = lane; j < GATE_H; j += 32) {
        const float hv = h[(size_t)warp * GATE_H + j];
        const float4 w0 = *reinterpret_cast<const float4*>(W + (size_t)j * NEXP);
        const float4 w1 = *reinterpret_cast<const float4*>(W + (size_t)j * NEXP + 4);
        acc[0] = fmaf(hv, w0.x, acc[0]); acc[1] = fmaf(hv, w0.y, acc[1]);
        acc[2] = fmaf(hv, w0.z, acc[2]); acc[3] = fmaf(hv, w0.w, acc[3]);
        acc[4] = fmaf(hv, w1.x, acc[4]); acc[5] = fmaf(hv, w1.y, acc[5]);
        acc[6] = fmaf(hv, w1.z, acc[6]); acc[7] = fmaf(hv, w1.w, acc[7]);
    }
#pragma unroll
    for (int e = 0; e < NEXP; e++)
#pragma unroll
        for (int o = 16; o > 0; o >>= 1)
            acc[e] += __shfl_down_sync(0xffffffffu, acc[e], o);
    if (lane == 0) {
        float v[NEXP], m = -1e30f;
#pragma unroll
        for (int e = 0; e < NEXP; e++) { v[e] = acc[e] + bias[e]; m = fmaxf(m, v[e]); }
        float sum = 0.f;
#pragma unroll
        for (int e = 0; e < NEXP; e++) { v[e] = __expf(v[e] - m); sum += v[e]; }
        const float inv = 1.f / sum;
#pragma unroll
        for (int e = 0; e < NEXP; e++) coeff[(size_t)warp * NEXP + e] = v[e] * inv;
    }
}

// ---------------------------------------------------------------------------
extern "C" void kernel_launch(void* const* d_in, const int* in_sizes, int n_in,
                              void* d_out, int out_size)
{
    const float* z = (const float*)d_in[0];
    const float* c = (const float*)d_in[1];
    const float *w[5], *bb[5], *lng[5], *lnb[5], *gW[3], *gbv[3];

    const bool dict_order = (in_sizes[4] == INPUTD);
    if (dict_order) {
        for (int i = 0; i < 5; i++) {
            w[i]   = (const float*)d_in[2 + 4 * i];
            bb[i]  = (const float*)d_in[3 + 4 * i];
            lng[i] = (const float*)d_in[4 + 4 * i];
            lnb[i] = (const float*)d_in[5 + 4 * i];
        }
    } else {
        for (int i = 0; i < 5; i++) {
            w[i]   = (const float*)d_in[2 + 2 * i];
            bb[i]  = (const float*)d_in[3 + 2 * i];
            lng[i] = (const float*)d_in[12 + 2 * i];
            lnb[i] = (const float*)d_in[13 + 2 * i];
        }
    }
    for (int j = 0; j < 3; j++) {
        gW[j]  = (const float*)d_in[22 + 2 * j];
        gbv[j] = (const float*)d_in[23 + 2 * j];
    }

    float *h1, *h2, *coeff, *loA, *loB;
    float2* stats;
    __half* wt;
    cudaGetSymbolAddress((void**)&h1,    g_h1);
    cudaGetSymbolAddress((void**)&h2,    g_h2);
    cudaGetSymbolAddress((void**)&coeff, g_coeff);
    cudaGetSymbolAddress((void**)&loA,   g_loA);
    cudaGetSymbolAddress((void**)&loB,   g_loB);
    cudaGetSymbolAddress((void**)&stats, g_stats);
    cudaGetSymbolAddress((void**)&wt,    g_wt);

    cudaFuncSetAttribute(h16gemm_kernel<1, 0>, cudaFuncAttributeMaxDynamicSharedMemorySize, SMEM_TOTAL);
    cudaFuncSetAttribute(h16gemm_kernel<0, 0>, cudaFuncAttributeMaxDynamicSharedMemorySize, SMEM_TOTAL);
    cudaFuncSetAttribute(h16gemm_kernel<2, 1>, cudaFuncAttributeMaxDynamicSharedMemorySize, SMEM_TOTAL);
    cudaFuncSetAttribute(h16gemm_kernel<2, 2>, cudaFuncAttributeMaxDynamicSharedMemorySize, SMEM_TOTAL);
    cudaFuncSetAttribute(h16gemm_kernel<2, 3>, cudaFuncAttributeMaxDynamicSharedMemorySize, SMEM_TOTAL);

    // ---- pre-transpose + fp16-convert weights: [K][N] f32 -> [N][K] f16 ----
    {
        const struct { const float* src; uint64_t off; int R, C; } cv[7] = {
            { w[0],  WT0_OFF,  10240, 1024 },
            { w[1],  WT1_OFF,  14336, 1024 },
            { w[2],  WT2_OFF,  14336, 1024 },
            { w[3],  WT3_OFF,  14336, 1024 },
            { w[4],  WT4_OFF,  14336, 512  },
            { gW[0], GWT0_OFF, 1280,  512  },
            { gW[1], GWT1_OFF, 512,   512  },
        };
        for (int i = 0; i < 7; i++)
            transpose_h_kernel<<<dim3(cv[i].C / 32, cv[i].R / 32), 256>>>(
                cv[i].src, wt + cv[i].off, cv[i].R, cv[i].C);
    }

    // ---- gate MLP ----
    h16gemm_kernel<1, 0><<<dim3(GATE_H / 128, Bsz / 128), 256, SMEM_TOTAL>>>(
        z, c, nullptr, wt + GWT0_OFF, gbv[0], nullptr, nullptr, nullptr, nullptr,
        h1, Bsz, GATE_H, INPUTD, 0);
    h16gemm_kernel<0, 0><<<dim3(GATE_H / 128, Bsz / 128), 256, SMEM_TOTAL>>>(
        h1, nullptr, nullptr, wt + GWT1_OFF, gbv[1], nullptr, nullptr, nullptr, nullptr,
        h2, Bsz, GATE_H, GATE_H, 0);
    gate2_kernel<<<(Bsz * 32 + 255) / 256, 256>>>(h2, gW[2], gbv[2], coeff);

    // ---- layer 0 (LN + mixed bias fused); writes loA ----
    ln_stats_kernel<<<Bsz, 256>>>(z, c, COND, stats, INPUTD);
    h16gemm_kernel<2, 1><<<dim3(HIDDEN / 128, Bsz / 128), 256, SMEM_TOTAL>>>(
        z, c, coeff, wt + WT0_OFF, bb[0], nullptr, lng[0], lnb[0], stats,
        loA, Bsz, HIDDEN, NEXP * INPUTD, INPUTD);

    // ---- layers 1..3 (residual), ping-pong loA/loB ----
    const uint64_t wtoff[3] = { WT1_OFF, WT2_OFF, WT3_OFF };
    float* lin = loA;
    float* lout = loB;
    for (int i = 1; i <= 3; i++) {
        ln_stats_kernel<<<Bsz, 256>>>(z, lin, HIDDEN, stats, INTERD);
        h16gemm_kernel<2, 2><<<dim3(HIDDEN / 128, Bsz / 128), 256, SMEM_TOTAL>>>(
            z, lin, coeff, wt + wtoff[i - 1], bb[i], lin, lng[i], lnb[i], stats,
            lout, Bsz, HIDDEN, NEXP * INTERD, INTERD);
        float* t = lin; lin = lout; lout = t;
    }

    // ---- final layer: reads lin, writes d_out ----
    ln_stats_kernel<<<Bsz, 256>>>(z, lin, HIDDEN, stats, INTERD);
    h16gemm_kernel<2, 3><<<dim3(OUTD / 128, Bsz / 128), 256, SMEM_TOTAL>>>(
        z, lin, coeff, wt + WT4_OFF, bb[4], nullptr, lng[4], lnb[4], stats,
        (float*)d_out, Bsz, OUTD, NEXP * INTERD, INTERD);
}

// round 17
// speedup vs baseline: 1.4538x; 1.4303x over previous
#include <cuda_runtime.h>
#include <cuda_fp16.h>
#include <cuda_bf16.h>
#include <math.h>
#include <stdint.h>

// ---------------------------------------------------------------------------
// GatingMixedDecoder: gate MLP -> softmax coeff -> 5 soft-mixed expert layers.
// mix(coeff,x,w) as one GEMM with K = E*d1. LayerNorm output pre-materialized
// as fp16 xh[B][d1]; GEMM A-path is pure cp.async; per-expert coeff applied to
// A fragments via HMUL2 (coeffs refreshed at expert boundaries).
// fp16 mma m16n8k16, f32 accumulate. Mixed expert bias fused into epilogue.
// ---------------------------------------------------------------------------

#define Bsz    4096
#define LATENT 768
#define COND   512
#define HIDDEN 1024
#define OUTD   512
#define NEXP   8
#define GATE_H 512
#define INPUTD 1280   // LATENT+COND
#define INTERD 1792   // LATENT+HIDDEN
#define NEG_SLOPE 0.01f
#define LN_EPS 1e-5f

// ---- scratch (device globals; no allocation allowed) ----
__device__ float  g_h1[Bsz * GATE_H];
__device__ float  g_h2[Bsz * GATE_H];
__device__ float  g_coeff[Bsz * NEXP];
__device__ float  g_lo[Bsz * HIDDEN];
__device__ __half g_xh[Bsz * INTERD];     // normalized concat row, fp16

// fp16 transposed weights, layout [N][K]
#define WT0_OFF   0ull                                   // [1024][10240]
#define WT1_OFF   (WT0_OFF + 1024ull * 10240ull)         // [1024][14336]
#define WT2_OFF   (WT1_OFF + 1024ull * 14336ull)
#define WT3_OFF   (WT2_OFF + 1024ull * 14336ull)
#define WT4_OFF   (WT3_OFF + 1024ull * 14336ull)         // [512][14336]
#define GWT0_OFF  (WT4_OFF + 512ull * 14336ull)          // [512][1280]
#define GWT1_OFF  (GWT0_OFF + 512ull * 1280ull)          // [512][512]
#define WT_TOTAL  (GWT1_OFF + 512ull * 512ull)
__device__ __half g_wt[WT_TOTAL];

__device__ __forceinline__ uint32_t smem_u32(const void* p) {
    uint32_t a;
    asm("{ .reg .u64 t; cvta.to.shared.u64 t, %1; cvt.u32.u64 %0, t; }" : "=r"(a) : "l"(p));
    return a;
}

// ---------------------------------------------------------------------------
// transpose + fp16 convert: out[c][r] = half(in[r][c]).  R%64==0, C%32==0.
// 64x32 tile per CTA, half2 stores.
// ---------------------------------------------------------------------------
__global__ void __launch_bounds__(256)
transpose_h_kernel(const float* __restrict__ in, __half* __restrict__ out, int R, int C)
{
    __shared__ float t[64][33];
    const int rb = blockIdx.y * 64, cb = blockIdx.x * 32;
    const int tx = threadIdx.x & 31, ty = threadIdx.x >> 5;   // 32x8
#pragma unroll
    for (int rr = ty; rr < 64; rr += 8)
        t[rr][tx] = in[(size_t)(rb + rr) * C + cb + tx];
    __syncthreads();
#pragma unroll
    for (int i = ty; i < 32; i += 8) {
        __half2 v = __halves2half2(__float2half_rn(t[2 * tx][i]),
                                   __float2half_rn(t[2 * tx + 1][i]));
        *reinterpret_cast<__half2*>(out + (size_t)(cb + i) * R + rb + 2 * tx) = v;
    }
}

// ---------------------------------------------------------------------------
// LayerNorm over concat(z[768], src[srclen]) -> xh fp16 [row][d]
// ---------------------------------------------------------------------------
__global__ void __launch_bounds__(256)
ln_norm_h_kernel(const float* __restrict__ z, const float* __restrict__ src,
                 int srclen, const float* __restrict__ g, const float* __restrict__ b,
                 __half* __restrict__ xh, int d)
{
    const int row = blockIdx.x;
    __shared__ float buf[INTERD];
    __shared__ float ws[8], wq[8];
    __shared__ float mu_s, rstd_s;
    const int tid = threadIdx.x, wid = tid >> 5, lane = tid & 31;

    float s = 0.f, sq = 0.f;
    for (int j = tid; j < d; j += 256) {
        float v = (j < LATENT) ? z[(size_t)row * LATENT + j]
                               : src[(size_t)row * srclen + (j - LATENT)];
        buf[j] = v;
        s += v; sq = fmaf(v, v, sq);
    }
#pragma unroll
    for (int o = 16; o > 0; o >>= 1) {
        s  += __shfl_down_sync(0xffffffffu, s, o);
        sq += __shfl_down_sync(0xffffffffu, sq, o);
    }
    if (lane == 0) { ws[wid] = s; wq[wid] = sq; }
    __syncthreads();
    if (tid == 0) {
        float S = 0.f, Q = 0.f;
#pragma unroll
        for (int i = 0; i < 8; i++) { S += ws[i]; Q += wq[i]; }
        const float mu = S / d;
        mu_s = mu;
        rstd_s = rsqrtf(Q / d - mu * mu + LN_EPS);
    }
    __syncthreads();
    const float mu = mu_s, rstd = rstd_s;
    for (int j = tid; j < d; j += 256)
        xh[(size_t)row * d + j] =
            __float2half_rn(fmaf((buf[j] - mu) * rstd, g[j], b[j]));
}

// ---------------------------------------------------------------------------
// fp16 tensor-core GEMM (f32 accum): C[M,N] = A[M,K] @ Bt[N,K]^T (+ epilogue)
// BM=128 BN=128 BK=32, 256 threads (8 warps), warp tile 64x32 (m16n8k16).
// Double-buffered smem; Bt via cp.async (fp16).
// AMODE 0: plain A1[M,K] f32 (register path).
// AMODE 1: concat(z[768], A2) f32 (register path).
// AMODE 3: MoE: A tile = Xh[b][(kt%tpe)*32 ...] fp16 via cp.async; per-expert
//          coeff[b, kt/tpe] applied to A fragments via HMUL2.
// EPI 0: + addend[n] (gate bias), leaky.
// EPI 1: + sum_e coeff[b,e]*biasE[e][n], leaky.          (addend = biasE[E][N])
// EPI 2: + mixed bias + resid[b,n], leaky.   (resid may alias C: element-owned)
// EPI 3: + mixed bias, no activation.
// ---------------------------------------------------------------------------
#define AH_STRIDE 40                       // halves per A row (32 + 8 pad)
#define BH_STRIDE 40                       // halves per Bt row (32 + 8 pad)
#define A_BYTES   (128 * AH_STRIDE * 2)    // 10240
#define B_BYTES   (128 * BH_STRIDE * 2)    // 10240
#define STAGE_BYTES (A_BYTES + B_BYTES)    // 20480
#define BIAS_BYTES  (NEXP * 128 * 4)       // 4096
#define SMEM_TOTAL (2 * STAGE_BYTES + BIAS_BYTES)   // 45056

template <int AMODE, int EPI>
__global__ void __launch_bounds__(256)
h16gemm_kernel(const float* __restrict__ A1, const float* __restrict__ A2,
               const float* __restrict__ coeff, const __half* __restrict__ Bt,
               const float* __restrict__ addend, const float* __restrict__ resid,
               const __half* __restrict__ Xh,
               float* __restrict__ C, int M, int N, int K, int d1)
{
    extern __shared__ char smem[];
    const uint32_t smem_base = smem_u32(smem);
    float* bs = reinterpret_cast<float*>(smem + 2 * STAGE_BYTES);  // [8][128]

    const int tid  = threadIdx.x;
    const int warp = tid >> 5;
    const int lane = tid & 31;
    const int warp_m = (warp >> 2) * 64;
    const int warp_n = (warp & 3) * 32;
    const int grp = lane >> 2;     // 0..7
    const int tig = lane & 3;      // 0..3

    const int bm = blockIdx.y * 128;
    const int bn = blockIdx.x * 128;

    // stage expert-bias tile into smem (EPI 1..3): bs[e][n] = biasE[e][bn+n]
    if (EPI != 0) {
        const int r = tid >> 5, cc = (tid & 31) * 4;
        *reinterpret_cast<float4*>(bs + r * 128 + cc) =
            *reinterpret_cast<const float4*>(addend + (size_t)r * N + bn + cc);
    }

    float acc[4][4][4];
#pragma unroll
    for (int i = 0; i < 4; i++)
#pragma unroll
        for (int j = 0; j < 4; j++)
#pragma unroll
            for (int r = 0; r < 4; r++) acc[i][j][r] = 0.f;

    float4 a_reg[4];            // AMODE 0/1 register staging
    unsigned cfa[4], cfb[4];    // AMODE 3: per-row expert coeff, half2-bcast
#pragma unroll
    for (int i = 0; i < 4; i++) { cfa[i] = 0u; cfb[i] = 0u; }

    // ---- A tile via registers (AMODE 0/1) ----
#define LOADA(k0)                                                               \
    {                                                                           \
        _Pragma("unroll")                                                       \
        for (int i = 0; i < 4; i++) {                                           \
            const int idx = tid + i * 256;                                      \
            const int row = idx >> 3, c4 = idx & 7;                             \
            const int gm = bm + row, gk = (k0) + c4 * 4;                        \
            if (AMODE == 0) {                                                   \
                a_reg[i] = *reinterpret_cast<const float4*>(A1 + (size_t)gm * K + gk); \
            } else {                                                            \
                if (gk < LATENT)                                                \
                    a_reg[i] = *reinterpret_cast<const float4*>(A1 + (size_t)gm * LATENT + gk); \
                else                                                            \
                    a_reg[i] = *reinterpret_cast<const float4*>(A2 + (size_t)gm * (K - LATENT) + (gk - LATENT)); \
            }                                                                   \
        }                                                                       \
    }

#define STOREA(s)                                                               \
    {                                                                           \
        __half* Ah = reinterpret_cast<__half*>(smem + (s) * STAGE_BYTES);       \
        _Pragma("unroll")                                                       \
        for (int i = 0; i < 4; i++) {                                           \
            const int idx = tid + i * 256;                                      \
            const int row = idx >> 3, c4 = idx & 7;                             \
            __half2 h0 = __float22half2_rn(make_float2(a_reg[i].x, a_reg[i].y)); \
            __half2 h1 = __float22half2_rn(make_float2(a_reg[i].z, a_reg[i].w)); \
            uint2 pk = make_uint2(*reinterpret_cast<uint32_t*>(&h0),            \
                                  *reinterpret_cast<uint32_t*>(&h1));           \
            *reinterpret_cast<uint2*>(Ah + row * AH_STRIDE + c4 * 4) = pk;      \
        }                                                                       \
    }

    // ---- A tile via cp.async from Xh (AMODE 3); jj0 = column base in xh ----
#define CPA3(s, jj0)                                                            \
    {                                                                           \
        const uint32_t abase = smem_base + (s) * STAGE_BYTES;                   \
        _Pragma("unroll")                                                       \
        for (int i = 0; i < 2; i++) {                                           \
            const int idx = tid + i * 256;                                      \
            const int row = idx >> 2, c8 = (idx & 3) * 8;                       \
            const uint32_t dst = abase + (uint32_t)(row * AH_STRIDE + c8) * 2;  \
            const __half* src = Xh + (size_t)(bm + row) * d1 + (jj0) + c8;      \
            asm volatile("cp.async.cg.shared.global [%0], [%1], 16;"            \
                         :: "r"(dst), "l"(src));                                \
        }                                                                       \
    }

#define CPB(s, k0)                                                              \
    {                                                                           \
        const uint32_t bbase = smem_base + (s) * STAGE_BYTES + A_BYTES;         \
        _Pragma("unroll")                                                       \
        for (int i = 0; i < 2; i++) {                                           \
            const int idx = tid + i * 256;                                      \
            const int n = idx >> 2, c4 = idx & 3;                               \
            const uint32_t dst = bbase + (uint32_t)(n * BH_STRIDE + c4 * 8) * 2; \
            const __half* src = Bt + (size_t)(bn + n) * K + (k0) + c4 * 8;      \
            asm volatile("cp.async.cg.shared.global [%0], [%1], 16;"            \
                         :: "r"(dst), "l"(src));                                \
        }                                                                       \
        asm volatile("cp.async.commit_group;");                                 \
    }

    const int nt = K >> 5;
    const int tpe = d1 >> 5;   // k-tiles per expert (AMODE 3)

    // prologue: fill stage 0
    if (AMODE == 3) {
        CPA3(0, 0);
        CPB(0, 0);
    } else {
        LOADA(0);
        CPB(0, 0);
        STOREA(0);
    }
    asm volatile("cp.async.wait_group 0;");
    __syncthreads();

    int pjj = 32;              // column base in xh for the next prefetched tile
    if (AMODE == 3 && pjj >= d1) pjj = 0;
    int ec = 0, e = -1;        // expert window counter (compute side)

    for (int kt = 0; kt < nt; kt++) {
        const int s = kt & 1;
        if (kt + 1 < nt) {
            if (AMODE == 3) {
                CPA3(s ^ 1, pjj);
                pjj += 32; if (pjj >= d1) pjj = 0;
            } else {
                LOADA((kt + 1) << 5);
            }
            CPB(s ^ 1, (kt + 1) << 5);
        }

        if (AMODE == 3) {
            if (ec == 0) {
                e += 1; ec = tpe;
#pragma unroll
                for (int mt = 0; mt < 4; mt++) {
                    const int r0 = bm + warp_m + mt * 16 + grp;
                    const float c0 = __ldg(coeff + (size_t)r0 * NEXP + e);
                    const float c1 = __ldg(coeff + (size_t)(r0 + 8) * NEXP + e);
                    __half2 h0 = __half2half2(__float2half_rn(c0));
                    __half2 h1 = __half2half2(__float2half_rn(c1));
                    cfa[mt] = *reinterpret_cast<uint32_t*>(&h0);
                    cfb[mt] = *reinterpret_cast<uint32_t*>(&h1);
                }
            }
            ec--;
        }

        const __half* Ah = reinterpret_cast<const __half*>(smem + s * STAGE_BYTES);
        const __half* Bh = reinterpret_cast<const __half*>(smem + s * STAGE_BYTES + A_BYTES);

#pragma unroll
        for (int ks = 0; ks < 2; ks++) {
            const int kk = ks * 16;
            unsigned bfr[4][2];
#pragma unroll
            for (int ntt = 0; ntt < 4; ntt++) {
                const int n = warp_n + ntt * 8 + grp;
                bfr[ntt][0] = *reinterpret_cast<const unsigned*>(Bh + n * BH_STRIDE + kk + tig * 2);
                bfr[ntt][1] = *reinterpret_cast<const unsigned*>(Bh + n * BH_STRIDE + kk + tig * 2 + 8);
            }
            unsigned afr[4][4];
#pragma unroll
            for (int mt = 0; mt < 4; mt++) {
                const int m = warp_m + mt * 16 + grp;
                afr[mt][0] = *reinterpret_cast<const unsigned*>(Ah + m * AH_STRIDE + kk + tig * 2);
                afr[mt][1] = *reinterpret_cast<const unsigned*>(Ah + (m + 8) * AH_STRIDE + kk + tig * 2);
                afr[mt][2] = *reinterpret_cast<const unsigned*>(Ah + m * AH_STRIDE + kk + tig * 2 + 8);
                afr[mt][3] = *reinterpret_cast<const unsigned*>(Ah + (m + 8) * AH_STRIDE + kk + tig * 2 + 8);
                if (AMODE == 3) {
                    __half2 ca = *reinterpret_cast<__half2*>(&cfa[mt]);
                    __half2 cb = *reinterpret_cast<__half2*>(&cfb[mt]);
                    __half2 t;
                    t = __hmul2(*reinterpret_cast<__half2*>(&afr[mt][0]), ca);
                    afr[mt][0] = *reinterpret_cast<uint32_t*>(&t);
                    t = __hmul2(*reinterpret_cast<__half2*>(&afr[mt][1]), cb);
                    afr[mt][1] = *reinterpret_cast<uint32_t*>(&t);
                    t = __hmul2(*reinterpret_cast<__half2*>(&afr[mt][2]), ca);
                    afr[mt][2] = *reinterpret_cast<uint32_t*>(&t);
                    t = __hmul2(*reinterpret_cast<__half2*>(&afr[mt][3]), cb);
                    afr[mt][3] = *reinterpret_cast<uint32_t*>(&t);
                }
            }
#pragma unroll
            for (int mt = 0; mt < 4; mt++)
#pragma unroll
                for (int ntt = 0; ntt < 4; ntt++) {
                    asm volatile(
                        "mma.sync.aligned.m16n8k16.row.col.f32.f16.f16.f32 "
                        "{%0,%1,%2,%3}, {%4,%5,%6,%7}, {%8,%9}, {%0,%1,%2,%3};"
                        : "+f"(acc[mt][ntt][0]), "+f"(acc[mt][ntt][1]),
                          "+f"(acc[mt][ntt][2]), "+f"(acc[mt][ntt][3])
                        : "r"(afr[mt][0]), "r"(afr[mt][1]),
                          "r"(afr[mt][2]), "r"(afr[mt][3]),
                          "r"(bfr[ntt][0]), "r"(bfr[ntt][1]));
                }
        }

        if (AMODE != 3 && kt + 1 < nt) STOREA(s ^ 1);
        asm volatile("cp.async.wait_group 0;");
        __syncthreads();
    }

    // ---- epilogue ----
#pragma unroll
    for (int mt = 0; mt < 4; mt++) {
        const int r0 = bm + warp_m + mt * 16 + grp;
#pragma unroll
        for (int half = 0; half < 2; half++) {
            const int gr = r0 + half * 8;
            float cf[NEXP];
            if (EPI != 0) {
                const float4 c0v = __ldg(reinterpret_cast<const float4*>(coeff + (size_t)gr * NEXP));
                const float4 c1v = __ldg(reinterpret_cast<const float4*>(coeff + (size_t)gr * NEXP + 4));
                cf[0] = c0v.x; cf[1] = c0v.y; cf[2] = c0v.z; cf[3] = c0v.w;
                cf[4] = c1v.x; cf[5] = c1v.y; cf[6] = c1v.z; cf[7] = c1v.w;
            }
#pragma unroll
            for (int ntt = 0; ntt < 4; ntt++) {
                const int ln0 = warp_n + ntt * 8 + tig * 2;   // local col in [0,128)
                const int c0 = bn + ln0;
                float v0 = acc[mt][ntt][half * 2 + 0];
                float v1 = acc[mt][ntt][half * 2 + 1];
                if (EPI == 0) {
                    const float2 ad = *reinterpret_cast<const float2*>(addend + c0);
                    v0 += ad.x; v1 += ad.y;
                } else {
#pragma unroll
                    for (int ee = 0; ee < NEXP; ee++) {
                        v0 = fmaf(cf[ee], bs[ee * 128 + ln0], v0);
                        v1 = fmaf(cf[ee], bs[ee * 128 + ln0 + 1], v1);
                    }
                }
                if (EPI == 2) {
                    const float2 rs = *reinterpret_cast<const float2*>(resid + (size_t)gr * N + c0);
                    v0 += rs.x; v1 += rs.y;
                }
                if (EPI != 3) {
                    v0 = (v0 > 0.f) ? v0 : NEG_SLOPE * v0;
                    v1 = (v1 > 0.f) ? v1 : NEG_SLOPE * v1;
                }
                *reinterpret_cast<float2*>(C + (size_t)gr * N + c0) = make_float2(v0, v1);
            }
        }
    }
#undef LOADA
#undef STOREA
#undef CPA3
#undef CPB
}

// ---------------------------------------------------------------------------
// gate layer 3 + softmax (one warp per row)
// ---------------------------------------------------------------------------
__global__ void __launch_bounds__(256)
gate2_kernel(const float* __restrict__ h, const float* __restrict__ W,
             const float* __restrict__ bias, float* __restrict__ coeff)
{
    const int warp = (blockIdx.x * blockDim.x + threadIdx.x) >> 5;
    const int lane = threadIdx.x & 31;
    if (warp >= Bsz) return;

    float acc[NEXP];
#pragma unroll
    for (int e = 0; e < NEXP; e++) acc[e] = 0.f;
    for (int j = lane; j < GATE_H; j += 32) {
        const float hv = h[(size_t)warp * GATE_H + j];
        const float4 w0 = *reinterpret_cast<const float4*>(W + (size_t)j * NEXP);
        const float4 w1 = *reinterpret_cast<const float4*>(W + (size_t)j * NEXP + 4);
        acc[0] = fmaf(hv, w0.x, acc[0]); acc[1] = fmaf(hv, w0.y, acc[1]);
        acc[2] = fmaf(hv, w0.z, acc[2]); acc[3] = fmaf(hv, w0.w, acc[3]);
        acc[4] = fmaf(hv, w1.x, acc[4]); acc[5] = fmaf(hv, w1.y, acc[5]);
        acc[6] = fmaf(hv, w1.z, acc[6]); acc[7] = fmaf(hv, w1.w, acc[7]);
    }
#pragma unroll
    for (int e = 0; e < NEXP; e++)
#pragma unroll
        for (int o = 16; o > 0; o >>= 1)
            acc[e] += __shfl_down_sync(0xffffffffu, acc[e], o);
    if (lane == 0) {
        float v[NEXP], m = -1e30f;
#pragma unroll
        for (int e = 0; e < NEXP; e++) { v[e] = acc[e] + bias[e]; m = fmaxf(m, v[e]); }
        float sum = 0.f;
#pragma unroll
        for (int e = 0; e < NEXP; e++) { v[e] = __expf(v[e] - m); sum += v[e]; }
        const float inv = 1.f / sum;
#pragma unroll
        for (int e = 0; e < NEXP; e++) coeff[(size_t)warp * NEXP + e] = v[e] * inv;
    }
}

// ---------------------------------------------------------------------------
extern "C" void kernel_launch(void* const* d_in, const int* in_sizes, int n_in,
                              void* d_out, int out_size)
{
    const float* z = (const float*)d_in[0];
    const float* c = (const float*)d_in[1];
    const float *w[5], *bb[5], *lng[5], *lnb[5], *gW[3], *gbv[3];

    const bool dict_order = (in_sizes[4] == INPUTD);
    if (dict_order) {
        for (int i = 0; i < 5; i++) {
            w[i]   = (const float*)d_in[2 + 4 * i];
            bb[i]  = (const float*)d_in[3 + 4 * i];
            lng[i] = (const float*)d_in[4 + 4 * i];
            lnb[i] = (const float*)d_in[5 + 4 * i];
        }
    } else {
        for (int i = 0; i < 5; i++) {
            w[i]   = (const float*)d_in[2 + 2 * i];
            bb[i]  = (const float*)d_in[3 + 2 * i];
            lng[i] = (const float*)d_in[12 + 2 * i];
            lnb[i] = (const float*)d_in[13 + 2 * i];
        }
    }
    for (int j = 0; j < 3; j++) {
        gW[j]  = (const float*)d_in[22 + 2 * j];
        gbv[j] = (const float*)d_in[23 + 2 * j];
    }

    float *h1, *h2, *coeff, *lo;
    __half *wt, *xh;
    cudaGetSymbolAddress((void**)&h1,    g_h1);
    cudaGetSymbolAddress((void**)&h2,    g_h2);
    cudaGetSymbolAddress((void**)&coeff, g_coeff);
    cudaGetSymbolAddress((void**)&lo,    g_lo);
    cudaGetSymbolAddress((void**)&xh,    g_xh);
    cudaGetSymbolAddress((void**)&wt,    g_wt);

    cudaFuncSetAttribute(h16gemm_kernel<1, 0>, cudaFuncAttributeMaxDynamicSharedMemorySize, SMEM_TOTAL);
    cudaFuncSetAttribute(h16gemm_kernel<0, 0>, cudaFuncAttributeMaxDynamicSharedMemorySize, SMEM_TOTAL);
    cudaFuncSetAttribute(h16gemm_kernel<3, 1>, cudaFuncAttributeMaxDynamicSharedMemorySize, SMEM_TOTAL);
    cudaFuncSetAttribute(h16gemm_kernel<3, 2>, cudaFuncAttributeMaxDynamicSharedMemorySize, SMEM_TOTAL);
    cudaFuncSetAttribute(h16gemm_kernel<3, 3>, cudaFuncAttributeMaxDynamicSharedMemorySize, SMEM_TOTAL);

    // ---- pre-transpose + fp16-convert weights: [K][N] f32 -> [N][K] f16 ----
    {
        const struct { const float* src; uint64_t off; int R, C; } cv[7] = {
            { w[0],  WT0_OFF,  10240, 1024 },
            { w[1],  WT1_OFF,  14336, 1024 },
            { w[2],  WT2_OFF,  14336, 1024 },
            { w[3],  WT3_OFF,  14336, 1024 },
            { w[4],  WT4_OFF,  14336, 512  },
            { gW[0], GWT0_OFF, 1280,  512  },
            { gW[1], GWT1_OFF, 512,   512  },
        };
        for (int i = 0; i < 7; i++)
            transpose_h_kernel<<<dim3(cv[i].C / 32, cv[i].R / 64), 256>>>(
                cv[i].src, wt + cv[i].off, cv[i].R, cv[i].C);
    }

    // ---- gate MLP ----
    h16gemm_kernel<1, 0><<<dim3(GATE_H / 128, Bsz / 128), 256, SMEM_TOTAL>>>(
        z, c, nullptr, wt + GWT0_OFF, gbv[0], nullptr, nullptr,
        h1, Bsz, GATE_H, INPUTD, 0);
    h16gemm_kernel<0, 0><<<dim3(GATE_H / 128, Bsz / 128), 256, SMEM_TOTAL>>>(
        h1, nullptr, nullptr, wt + GWT1_OFF, gbv[1], nullptr, nullptr,
        h2, Bsz, GATE_H, GATE_H, 0);
    gate2_kernel<<<(Bsz * 32 + 255) / 256, 256>>>(h2, gW[2], gbv[2], coeff);

    // ---- layer 0: LN -> xh fp16, then GEMM (bias mixed in epilogue) ----
    ln_norm_h_kernel<<<Bsz, 256>>>(z, c, COND, lng[0], lnb[0], xh, INPUTD);
    h16gemm_kernel<3, 1><<<dim3(HIDDEN / 128, Bsz / 128), 256, SMEM_TOTAL>>>(
        nullptr, nullptr, coeff, wt + WT0_OFF, bb[0], nullptr, xh,
        lo, Bsz, HIDDEN, NEXP * INPUTD, INPUTD);

    // ---- layers 1..3 (residual; resid element-owned, safe in-place) ----
    const uint64_t wtoff[3] = { WT1_OFF, WT2_OFF, WT3_OFF };
    for (int i = 1; i <= 3; i++) {
        ln_norm_h_kernel<<<Bsz, 256>>>(z, lo, HIDDEN, lng[i], lnb[i], xh, INTERD);
        h16gemm_kernel<3, 2><<<dim3(HIDDEN / 128, Bsz / 128), 256, SMEM_TOTAL>>>(
            nullptr, nullptr, coeff, wt + wtoff[i - 1], bb[i], lo, xh,
            lo, Bsz, HIDDEN, NEXP * INTERD, INTERD);
    }

    // ---- final layer ----
    ln_norm_h_kernel<<<Bsz, 256>>>(z, lo, HIDDEN, lng[4], lnb[4], xh, INTERD);
    h16gemm_kernel<3, 3><<<dim3(OUTD / 128, Bsz / 128), 256, SMEM_TOTAL>>>(
        nullptr, nullptr, coeff, wt + WT4_OFF, bb[4], nullptr, xh,
        (float*)d_out, Bsz, OUTD, NEXP * INTERD, INTERD);
}